// round 13
// baseline (speedup 1.0000x reference)
#include <cuda_runtime.h>

#define CLS 128
#define BMAX (1 << 19)
#define EPSF 1e-7f
#define BETAF 1.0f
#define SPLITS 16

// ---- device-global scratch (no allocation allowed in kernel_launch) ----
__device__ int   g_is64;          // 1 if targets buffer is int64, 0 if int32
__device__ int   g_counts[CLS];
__device__ int   g_offsets[CLS];
__device__ int   g_cursor[CLS];
__device__ int   g_sorted[BMAX];
__device__ float g_sumP[CLS * CLS];
__device__ float g_sumLN[CLS * CLS];
__device__ float g_posSum[CLS];

// Load target i under either dtype. Mask keeps every index provably in-range.
__device__ __forceinline__ int load_tgt(const int* __restrict__ tgt, int i, int is64) {
    int v = is64 ? (int)(__ldg((const long long*)tgt + i)) : __ldg(tgt + i);
    return v & (CLS - 1);
}

// ---------------------------------------------------------------- dtype detect
// Reading int32 words [1,63] is safe in both layouts (buffer >= B*4 bytes).
// int64 little-endian with values < 2^31  =>  every odd int32 word is 0.
// For int32 random targets, 32 odd words all zero has prob 128^-32 ~ 0.
__global__ void k_detect(const int* __restrict__ tgt, int B) {
    if (blockIdx.x == 0 && threadIdx.x == 0) {
        int lim = (2 * B < 64) ? 2 * B : 64;   // stay inside int32 view of buffer
        int is64 = 1;
        for (int i = 1; i < lim; i += 2)
            if (__ldg(&tgt[i]) != 0) { is64 = 0; break; }
        g_is64 = is64;
    }
}

// ---------------------------------------------------------------- zero
__global__ void k_zero() {
    int i = blockIdx.x * blockDim.x + threadIdx.x;
    int stride = gridDim.x * blockDim.x;
    if (i < CLS) { g_counts[i] = 0; g_posSum[i] = 0.f; }
    for (int j = i; j < CLS * CLS; j += stride) {
        g_sumP[j]  = 0.f;
        g_sumLN[j] = 0.f;
    }
}

// ---------------------------------------------------------------- histogram
__global__ void k_hist(const int* __restrict__ tgt, int B) {
    __shared__ int sh[CLS];
    int t = threadIdx.x;
    int is64 = g_is64;
    for (int j = t; j < CLS; j += blockDim.x) sh[j] = 0;
    __syncthreads();
    for (int i = blockIdx.x * blockDim.x + t; i < B; i += gridDim.x * blockDim.x)
        atomicAdd(&sh[load_tgt(tgt, i, is64)], 1);
    __syncthreads();
    for (int j = t; j < CLS; j += blockDim.x)
        if (sh[j]) atomicAdd(&g_counts[j], sh[j]);
}

// ---------------------------------------------------------------- prefix (1 block, CLS threads)
__global__ void k_prefix() {
    __shared__ int sh[CLS];
    int t = threadIdx.x;
    int own = g_counts[t];
    sh[t] = own;
    __syncthreads();
    for (int d = 1; d < CLS; d <<= 1) {
        int add = (t >= d) ? sh[t - d] : 0;
        __syncthreads();
        sh[t] += add;
        __syncthreads();
    }
    int excl = sh[t] - own;
    g_offsets[t] = excl;
    g_cursor[t]  = excl;
}

// ---------------------------------------------------------------- scatter (block-aggregated)
// 256 blocks: spreads the shared-atomic chains across SMs (ATOMS serialize
// per bank; 4 elems/thread keeps per-block chains short).
#define SC_TPB 256
#define SC_PER 4
__global__ void k_scatter(const int* __restrict__ tgt, int B) {
    __shared__ int shh[CLS];  // block-local histogram
    __shared__ int shb[CLS];  // reserved base offsets
    int t = threadIdx.x;
    int is64 = g_is64;
    int tile = blockIdx.x * (SC_TPB * SC_PER);
    for (int j = t; j < CLS; j += SC_TPB) shh[j] = 0;
    __syncthreads();

    int cls[SC_PER];
    int rnk[SC_PER];
#pragma unroll
    for (int u = 0; u < SC_PER; u++) {
        int i = tile + u * SC_TPB + t;
        cls[u] = -1;
        rnk[u] = 0;
        if (i < B) {
            int c = load_tgt(tgt, i, is64);
            cls[u] = c;
            rnk[u] = atomicAdd(&shh[c], 1);
        }
    }
    __syncthreads();
    for (int j = t; j < CLS; j += SC_TPB)
        shb[j] = shh[j] ? atomicAdd(&g_cursor[j], shh[j]) : 0;
    __syncthreads();
#pragma unroll
    for (int u = 0; u < SC_PER; u++) {
        if (cls[u] >= 0)
            g_sorted[shb[cls[u]] + rnk[u]] = tile + u * SC_TPB + t;
    }
}

// ---------------------------------------------------------------- main reduction
// grid = (SPLITS, CLS), block = CLS threads; thread k owns column k of class c.
// Per element: EX2 + RCP + LG2 = 3 MUFU lane-ops (the binding pipe, ~24 us floor).
__device__ __forceinline__ void proc_elt(float xv, bool diag,
                                         float& sp, float& sl, float& lp) {
    float t = __expf(-xv);              // e^{-x}            (EX2)
    float p = __fdividef(1.f, 1.f + t); // sigmoid           (RCP)
    float q = fmaf(t, p, EPSF);         // (1-p)+eps  (t*p == 1-p exactly)
    sp += p;
    sl += __logf(q);                    // log(1-p+eps)      (LG2)
    if (diag) lp += __logf(p + EPSF);   // only thread k==c
}

__global__ void __launch_bounds__(CLS) k_main(const float* __restrict__ x) {
    int c     = blockIdx.y;
    int split = blockIdx.x;
    int k     = threadIdx.x;
    bool diag = (k == c);

    int cnt = g_counts[c];
    int off = g_offsets[c];
    int per = (cnt + SPLITS - 1) / SPLITS;
    int s = split * per;
    int e = min(cnt, s + per);

    const float* __restrict__ xk = x + k;   // column base, hoisted
    float sp = 0.f, sl = 0.f, lp = 0.f;

    int j = s;
    for (; j + 8 <= e; j += 8) {
        int r[8];
#pragma unroll
        for (int u = 0; u < 8; u++) r[u] = __ldg(&g_sorted[off + j + u]);
        float xv[8];
#pragma unroll
        for (int u = 0; u < 8; u++) xv[u] = __ldg(xk + (size_t)r[u] * CLS);
#pragma unroll
        for (int u = 0; u < 8; u++) proc_elt(xv[u], diag, sp, sl, lp);
    }
    for (; j < e; j++) {
        int r = __ldg(&g_sorted[off + j]);
        proc_elt(__ldg(xk + (size_t)r * CLS), diag, sp, sl, lp);
    }

    if (e > s) {
        atomicAdd(&g_sumP[c * CLS + k], sp);
        atomicAdd(&g_sumLN[c * CLS + k], sl);
        if (diag) atomicAdd(&g_posSum[c], lp);
    }
}

// ---------------------------------------------------------------- finalize (1 block, CLS threads)
__global__ void k_final(float* __restrict__ out) {
    __shared__ float red[CLS];
    __shared__ float sh_inv[CLS];
    __shared__ int   sh_present[CLS];
    int k = threadIdx.x;

    int cnt = g_counts[k];
    int present = (cnt > 0);
    float inv = present ? (1.f / (float)cnt) : 1.f;
    sh_inv[k] = inv;
    sh_present[k] = present;
    __syncthreads();

    // positive term: class k's mean log p over its own samples
    float acc = present ? (g_posSum[k] * inv) : 0.f;

    // negative term: column-k softmax over rows j (j != k, present[j]).
    // Reference's -1e30 entries contribute exp(-inf)=0 to the denominator,
    // identical to skipping them; fully-masked column => zero contribution.
    float m = -1e30f;
    for (int j = 0; j < CLS; j++) {
        if (j == k || !sh_present[j]) continue;
        float mp = BETAF * (g_sumP[j * CLS + k] * sh_inv[j]);
        m = fmaxf(m, mp);
    }
    if (m > -1e29f) {
        float se = 0.f, ws = 0.f;
        for (int j = 0; j < CLS; j++) {
            if (j == k || !sh_present[j]) continue;
            float mp = BETAF * (g_sumP[j * CLS + k] * sh_inv[j]);
            float w  = __expf(mp - m);
            se += w;
            ws += w * (g_sumLN[j * CLS + k] * sh_inv[j]);
        }
        acc += ws / se;
    }

    red[k] = acc;
    __syncthreads();
    for (int d = CLS / 2; d > 0; d >>= 1) {
        if (k < d) red[k] += red[k + d];
        __syncthreads();
    }
    if (k == 0) out[0] = -red[0];
}

// ---------------------------------------------------------------- launch
extern "C" void kernel_launch(void* const* d_in, const int* in_sizes, int n_in,
                              void* d_out, int out_size) {
    const float* x   = (const float*)d_in[0];
    const int*   tgt = (const int*)d_in[1];   // int32 or int64 view; k_detect decides
    int B = in_sizes[1];
    if (B > BMAX) B = BMAX;  // scratch bound (B=262144 fits; clamp is a safety net)

    k_detect<<<1, 32>>>(tgt, B);
    k_zero<<<148, 256>>>();
    k_hist<<<256, 256>>>(tgt, B);
    k_prefix<<<1, CLS>>>();
    int nsc = (B + SC_TPB * SC_PER - 1) / (SC_TPB * SC_PER);
    k_scatter<<<nsc, SC_TPB>>>(tgt, B);
    dim3 gmain(SPLITS, CLS);
    k_main<<<gmain, CLS>>>(x);
    k_final<<<1, CLS>>>((float*)d_out);
}

// round 14
// speedup vs baseline: 1.0613x; 1.0613x over previous
#include <cuda_runtime.h>

#define CLS 128
#define BMAX (1 << 19)
#define EPSF 1e-7f
#define BETAF 1.0f
#define SPLITS 16

// ---- device-global scratch (no allocation allowed in kernel_launch) ----
__device__ int   g_is64;          // 1 if targets buffer is int64, 0 if int32
__device__ int   g_counts[CLS];
__device__ int   g_offsets[CLS];
__device__ int   g_cursor[CLS];
__device__ int   g_sorted[BMAX];
__device__ float g_sumP[CLS * CLS];
__device__ float g_sumLN[CLS * CLS];
__device__ float g_posSum[CLS];

// Load target i under either dtype. Mask keeps every index provably in-range.
__device__ __forceinline__ int load_tgt(const int* __restrict__ tgt, int i, int is64) {
    int v = is64 ? (int)(__ldg((const long long*)tgt + i)) : __ldg(tgt + i);
    return v & (CLS - 1);
}

// ---------------------------------------------------------------- zero + dtype detect (fused)
// int64 little-endian values < 2^31 => every odd int32 word is 0.
// 32 random targets all == 0 has prob 128^-32 ~ 0 => detection deterministic.
__global__ void k_zero(const int* __restrict__ tgt, int B) {
    int i = blockIdx.x * blockDim.x + threadIdx.x;
    int stride = gridDim.x * blockDim.x;
    if (i == 0) {
        int lim = (2 * B < 64) ? 2 * B : 64;   // stay inside int32 view of buffer
        int is64 = 1;
        for (int j = 1; j < lim; j += 2)
            if (__ldg(&tgt[j]) != 0) { is64 = 0; break; }
        g_is64 = is64;
    }
    if (i < CLS) { g_counts[i] = 0; g_cursor[i] = 0; g_posSum[i] = 0.f; }
    for (int j = i; j < CLS * CLS; j += stride) {
        g_sumP[j]  = 0.f;
        g_sumLN[j] = 0.f;
    }
}

// ---------------------------------------------------------------- histogram
__global__ void k_hist(const int* __restrict__ tgt, int B) {
    __shared__ int sh[CLS];
    int t = threadIdx.x;
    int is64 = g_is64;
    for (int j = t; j < CLS; j += blockDim.x) sh[j] = 0;
    __syncthreads();
    for (int i = blockIdx.x * blockDim.x + t; i < B; i += gridDim.x * blockDim.x)
        atomicAdd(&sh[load_tgt(tgt, i, is64)], 1);
    __syncthreads();
    for (int j = t; j < CLS; j += blockDim.x)
        if (sh[j]) atomicAdd(&g_counts[j], sh[j]);
}

// ---------------------------------------------------------------- scatter + positive term
// Local smem prefix-scan of g_counts replaces the k_prefix kernel (saves one
// ~4.7us graph node). Also accumulates the positive term log(sigmoid(x[i,t_i])+eps)
// here — one scattered 4B load + 3 MUFU per ROW — so k_main loses its diag branch.
#define SC_TPB 256
#define SC_PER 4
__global__ void k_scatter(const int* __restrict__ tgt, const float* __restrict__ x, int B) {
    __shared__ int   shoff[CLS];  // exclusive prefix of g_counts
    __shared__ int   shh[CLS];    // block-local histogram
    __shared__ int   shb[CLS];    // reserved base ranks (global cursor)
    __shared__ float shp[CLS];    // block-local positive-term sums
    int t = threadIdx.x;
    int is64 = g_is64;
    int tile = blockIdx.x * (SC_TPB * SC_PER);

    // exclusive scan of g_counts (Hillis-Steele, 128 wide)
    if (t < CLS) shoff[t] = g_counts[t];
    for (int j = t; j < CLS; j += SC_TPB) { shh[j] = 0; shp[j] = 0.f; }
    __syncthreads();
    if (t < CLS) {
        int acc = shoff[t];
#pragma unroll
        for (int d = 1; d < CLS; d <<= 1) {
            int add = (t >= d) ? shoff[t - d] : 0;
            __syncthreads();
            shoff[t] = acc = acc + add;
            __syncthreads();
        }
        int excl = acc - g_counts[t];
        shoff[t] = excl;
        if (blockIdx.x == 0) g_offsets[t] = excl;   // publish for k_main
    } else {
        // keep barrier counts matched across the whole block
#pragma unroll
        for (int d = 1; d < CLS; d <<= 1) { __syncthreads(); __syncthreads(); }
    }
    __syncthreads();

    int   cls[SC_PER];
    int   rnk[SC_PER];
#pragma unroll
    for (int u = 0; u < SC_PER; u++) {
        int i = tile + u * SC_TPB + t;
        cls[u] = -1;
        rnk[u] = 0;
        if (i < B) {
            int c = load_tgt(tgt, i, is64);
            cls[u] = c;
            rnk[u] = atomicAdd(&shh[c], 1);
            // positive term: log(sigmoid(x[i,c]) + eps)
            float xv = __ldg(&x[(size_t)i * CLS + c]);
            float e  = __expf(-xv);
            float p  = __fdividef(1.f, 1.f + e);
            atomicAdd(&shp[c], __logf(p + EPSF));
        }
    }
    __syncthreads();
    for (int j = t; j < CLS; j += SC_TPB) {
        shb[j] = shh[j] ? atomicAdd(&g_cursor[j], shh[j]) : 0;
        if (shp[j] != 0.f) atomicAdd(&g_posSum[j], shp[j]);
    }
    __syncthreads();
#pragma unroll
    for (int u = 0; u < SC_PER; u++) {
        if (cls[u] >= 0)
            g_sorted[shoff[cls[u]] + shb[cls[u]] + rnk[u]] = tile + u * SC_TPB + t;
    }
}

// ---------------------------------------------------------------- main reduction
// grid = (SPLITS, CLS), block = CLS threads; thread k owns column k of class c.
// Exactly 3 MUFU lane-ops per element (EX2, RCP, LG2) — no diag branch anymore.
__device__ __forceinline__ void proc_elt(float xv, float& sp, float& sl) {
    float t = __expf(-xv);              // e^{-x}            (EX2)
    float p = __fdividef(1.f, 1.f + t); // sigmoid           (RCP)
    float q = fmaf(t, p, EPSF);         // (1-p)+eps  (t*p == 1-p exactly)
    sp += p;
    sl += __logf(q);                    // log(1-p+eps)      (LG2)
}

__global__ void __launch_bounds__(CLS) k_main(const float* __restrict__ x) {
    int c     = blockIdx.y;
    int split = blockIdx.x;
    int k     = threadIdx.x;

    int cnt = g_counts[c];
    int off = g_offsets[c];
    int per = (cnt + SPLITS - 1) / SPLITS;
    int s = split * per;
    int e = min(cnt, s + per);

    const float* __restrict__ xk = x + k;   // column base, hoisted
    float sp = 0.f, sl = 0.f;

    int j = s;
    for (; j + 8 <= e; j += 8) {
        int r[8];
#pragma unroll
        for (int u = 0; u < 8; u++) r[u] = __ldg(&g_sorted[off + j + u]);
        float xv[8];
#pragma unroll
        for (int u = 0; u < 8; u++) xv[u] = __ldg(xk + (size_t)r[u] * CLS);
#pragma unroll
        for (int u = 0; u < 8; u++) proc_elt(xv[u], sp, sl);
    }
    for (; j < e; j++) {
        int r = __ldg(&g_sorted[off + j]);
        proc_elt(__ldg(xk + (size_t)r * CLS), sp, sl);
    }

    if (e > s) {
        atomicAdd(&g_sumP[c * CLS + k], sp);
        atomicAdd(&g_sumLN[c * CLS + k], sl);
    }
}

// ---------------------------------------------------------------- finalize (1 block, CLS threads)
__global__ void k_final(float* __restrict__ out) {
    __shared__ float red[CLS];
    __shared__ float sh_inv[CLS];
    __shared__ int   sh_present[CLS];
    int k = threadIdx.x;

    int cnt = g_counts[k];
    int present = (cnt > 0);
    float inv = present ? (1.f / (float)cnt) : 1.f;
    sh_inv[k] = inv;
    sh_present[k] = present;
    __syncthreads();

    // positive term: class k's mean log p over its own samples
    float acc = present ? (g_posSum[k] * inv) : 0.f;

    // negative term: column-k softmax over rows j (j != k, present[j]).
    // Reference's -1e30 entries contribute exp(-inf)=0 to the denominator,
    // identical to skipping them; fully-masked column => zero contribution.
    float m = -1e30f;
    for (int j = 0; j < CLS; j++) {
        if (j == k || !sh_present[j]) continue;
        float mp = BETAF * (g_sumP[j * CLS + k] * sh_inv[j]);
        m = fmaxf(m, mp);
    }
    if (m > -1e29f) {
        float se = 0.f, ws = 0.f;
        for (int j = 0; j < CLS; j++) {
            if (j == k || !sh_present[j]) continue;
            float mp = BETAF * (g_sumP[j * CLS + k] * sh_inv[j]);
            float w  = __expf(mp - m);
            se += w;
            ws += w * (g_sumLN[j * CLS + k] * sh_inv[j]);
        }
        acc += ws / se;
    }

    red[k] = acc;
    __syncthreads();
    for (int d = CLS / 2; d > 0; d >>= 1) {
        if (k < d) red[k] += red[k + d];
        __syncthreads();
    }
    if (k == 0) out[0] = -red[0];
}

// ---------------------------------------------------------------- launch (5 graph nodes)
extern "C" void kernel_launch(void* const* d_in, const int* in_sizes, int n_in,
                              void* d_out, int out_size) {
    const float* x   = (const float*)d_in[0];
    const int*   tgt = (const int*)d_in[1];   // int32 or int64 view; k_zero detects
    int B = in_sizes[1];
    if (B > BMAX) B = BMAX;  // scratch bound (B=262144 fits; clamp is a safety net)

    k_zero<<<148, 256>>>(tgt, B);
    k_hist<<<256, 256>>>(tgt, B);
    int nsc = (B + SC_TPB * SC_PER - 1) / (SC_TPB * SC_PER);
    k_scatter<<<nsc, SC_TPB>>>(tgt, x, B);
    dim3 gmain(SPLITS, CLS);
    k_main<<<gmain, CLS>>>(x);
    k_final<<<1, CLS>>>((float*)d_out);
}